// round 11
// baseline (speedup 1.0000x reference)
#include <cuda_runtime.h>
#include <cuda_bf16.h>
#include <stdint.h>
#include <math.h>

#define NN 100000
#define NE 1600000
#define KDIM 512
#define F 64
#define NB 98        // ceil(NN/1024)

// ---------------- scratch (device globals; no allocation allowed) ----------
__device__ __align__(16) int   g_deg[NN];
__device__ __align__(16) float g_dinv[NN];
__device__ __align__(16) int   g_rowptr[NN];
__device__ __align__(16) int   g_cursor[NN];
__device__ __align__(16) int   g_blocksums[128];
__device__ __align__(16) int2  g_edge[NE];             // {src, weight bits}
__device__ __align__(16) float g_xw[(size_t)NN * F];   // x @ W1
__device__ __align__(16) float g_h [(size_t)NN * F];   // relu(Agg(xw)+b1)
// pre-split, pre-swizzled weight images (smem-ready)
__device__ __align__(16) uint4 g_w1h_img[4096];        // 8 chunks x 8KB
__device__ __align__(16) uint4 g_w1l_img[4096];
__device__ __align__(16) uint4 g_w2h_img[1024];        // 16KB: [Wmu|Wvar]^T
__device__ __align__(16) uint4 g_w2l_img[1024];

#define SMEM_SWIZZLE_128B(off) ((off) ^ (((off) >> 3) & 0x70))

__device__ __forceinline__ uint32_t smem_to_u32(const void* p) {
    uint32_t a;
    asm("{ .reg .u64 t; cvta.to.shared.u64 t, %1; cvt.u32.u64 %0, t; }"
        : "=r"(a) : "l"(p));
    return a;
}
__device__ __forceinline__ uint32_t pack_bf16x2(__nv_bfloat16 lo, __nv_bfloat16 hi) {
    __nv_bfloat162 t; t.x = lo; t.y = hi;
    return *reinterpret_cast<uint32_t*>(&t);
}
__device__ __forceinline__ uint32_t cvt_bf16x2(float hi, float lo) {
    uint32_t r;
    asm("cvt.rn.bf16x2.f32 %0, %1, %2;" : "=r"(r) : "f"(hi), "f"(lo));
    return r;
}
__device__ __forceinline__ void ldsm_x4(uint32_t& r0, uint32_t& r1, uint32_t& r2,
                                        uint32_t& r3, uint32_t addr) {
    asm volatile("ldmatrix.sync.aligned.m8n8.x4.shared.b16 {%0,%1,%2,%3}, [%4];"
                 : "=r"(r0), "=r"(r1), "=r"(r2), "=r"(r3) : "r"(addr));
}
__device__ __forceinline__ void mma_bf16(float* c, const uint32_t* a,
                                         const uint32_t* b) {
    asm volatile(
        "mma.sync.aligned.m16n8k16.row.col.f32.bf16.bf16.f32 "
        "{%0,%1,%2,%3}, {%4,%5,%6,%7}, {%8,%9}, {%0,%1,%2,%3};"
        : "+f"(c[0]), "+f"(c[1]), "+f"(c[2]), "+f"(c[3])
        : "r"(a[0]), "r"(a[1]), "r"(a[2]), "r"(a[3]), "r"(b[0]), "r"(b[1]));
}
__device__ __forceinline__ void split4(float4 v, uint2& hi, uint2& lo) {
    uint32_t ax = __float_as_uint(v.x), ay = __float_as_uint(v.y);
    uint32_t az = __float_as_uint(v.z), aw = __float_as_uint(v.w);
    hi.x = __byte_perm(ax, ay, 0x7632);
    hi.y = __byte_perm(az, aw, 0x7632);
    float rx = v.x - __uint_as_float(ax & 0xFFFF0000u);
    float ry = v.y - __uint_as_float(ay & 0xFFFF0000u);
    float rz = v.z - __uint_as_float(az & 0xFFFF0000u);
    float rw = v.w - __uint_as_float(aw & 0xFFFF0000u);
    lo.x = cvt_bf16x2(ry, rx);
    lo.y = cvt_bf16x2(rw, rz);
}
#define CP_ASYNC16(dst, src) \
    asm volatile("cp.async.cg.shared.global [%0], [%1], 16;" \
                 :: "r"(dst), "l"(src) : "memory")
#define CP_COMMIT() asm volatile("cp.async.commit_group;" ::: "memory")
#define CP_WAIT0()  asm volatile("cp.async.wait_group 0;" ::: "memory")

// ---------------- prep: zero ∥ splitW1 ∥ splitW2 (one launch) --------------
__global__ void __launch_bounds__(256) k_prep(const float* __restrict__ W1,
                                              const float* __restrict__ Wmu,
                                              const float* __restrict__ Wvar) {
    int bx = blockIdx.x;
    int tid = threadIdx.x;
    if (bx < 391) {                       // zero deg/cursor
        int i = bx * 256 + tid;
        if (i < NN) { g_deg[i] = 0; g_cursor[i] = 0; }
    } else if (bx < 407) {                // splitW1: 4096 granules
        int gid = (bx - 391) * 256 + tid;
        int c  = gid >> 9;
        int g  = gid & 511;
        int n  = g >> 3;
        int k8 = (g & 7) * 8;
        uint32_t hi[4], lo[4];
#pragma unroll
        for (int jj = 0; jj < 4; jj++) {
            float w0 = W1[(size_t)(c * 64 + k8 + jj * 2 + 0) * F + n];
            float w1 = W1[(size_t)(c * 64 + k8 + jj * 2 + 1) * F + n];
            __nv_bfloat16 a0 = __float2bfloat16(w0), a1 = __float2bfloat16(w1);
            __nv_bfloat16 b0 = __float2bfloat16(w0 - __bfloat162float(a0));
            __nv_bfloat16 b1 = __float2bfloat16(w1 - __bfloat162float(a1));
            hi[jj] = pack_bf16x2(a0, a1);
            lo[jj] = pack_bf16x2(b0, b1);
        }
        uint32_t off = SMEM_SWIZZLE_128B((uint32_t)(n * 128 + k8 * 2)) >> 4;
        g_w1h_img[c * 512 + off] = make_uint4(hi[0], hi[1], hi[2], hi[3]);
        g_w1l_img[c * 512 + off] = make_uint4(lo[0], lo[1], lo[2], lo[3]);
    } else {                              // splitW2: 1024 granules
        int gid = (bx - 407) * 256 + tid;
        int n  = gid >> 3;
        int k8 = (gid & 7) * 8;
        const float* Wsrc = (n < 64) ? Wmu : Wvar;
        int nn = n & 63;
        uint32_t hi[4], lo[4];
#pragma unroll
        for (int jj = 0; jj < 4; jj++) {
            float w0 = Wsrc[(size_t)(k8 + jj * 2 + 0) * 64 + nn];
            float w1 = Wsrc[(size_t)(k8 + jj * 2 + 1) * 64 + nn];
            __nv_bfloat16 a0 = __float2bfloat16(w0), a1 = __float2bfloat16(w1);
            __nv_bfloat16 b0 = __float2bfloat16(w0 - __bfloat162float(a0));
            __nv_bfloat16 b1 = __float2bfloat16(w1 - __bfloat162float(a1));
            hi[jj] = pack_bf16x2(a0, a1);
            lo[jj] = pack_bf16x2(b0, b1);
        }
        uint32_t off = SMEM_SWIZZLE_128B((uint32_t)(n * 128 + k8 * 2)) >> 4;
        g_w2h_img[off] = make_uint4(hi[0], hi[1], hi[2], hi[3]);
        g_w2l_img[off] = make_uint4(lo[0], lo[1], lo[2], lo[3]);
    }
}

// ---------------- CSR build ------------------------------------------------
__global__ void k_hist(const int* __restrict__ ei) {
    int e = blockIdx.x * blockDim.x + threadIdx.x;
    if (e < NE) atomicAdd(&g_deg[ei[NE + e]], 1);
}
__global__ void k_scan_local() {
    __shared__ int s[1024];
    int t = threadIdx.x;
    int i = blockIdx.x * 1024 + t;
    int v = (i < NN) ? g_deg[i] : 0;
    if (i < NN) g_dinv[i] = rsqrtf((float)v + 1.0f);
    s[t] = v; __syncthreads();
    for (int off = 1; off < 1024; off <<= 1) {
        int x = (t >= off) ? s[t - off] : 0;
        __syncthreads();
        s[t] += x;
        __syncthreads();
    }
    if (i < NN) g_rowptr[i] = s[t] - v;
    if (t == 1023) g_blocksums[blockIdx.x] = s[1023];
}
__global__ void k_scan_finish() {
    __shared__ int s[128];
    __shared__ int s_off;
    int t  = threadIdx.x;
    int bx = blockIdx.x;
    if (t < NB) s[t] = g_blocksums[t];
    __syncthreads();
    if (t == 0) {
        int acc = 0;
        for (int k = 0; k < bx; k++) acc += s[k];
        s_off = acc;
    }
    __syncthreads();
    int i = bx * 1024 + t;
    if (i < NN) g_rowptr[i] += s_off;
}
__global__ void k_scatter(const int* __restrict__ ei) {
    int e = blockIdx.x * blockDim.x + threadIdx.x;
    if (e >= NE) return;
    int src = ei[e];
    int dst = ei[NE + e];
    int pos = g_rowptr[dst] + atomicAdd(&g_cursor[dst], 1);
    g_edge[pos] = make_int2(src, __float_as_int(g_dinv[src] * g_dinv[dst]));
}

// ---------------- GEMM1: pipelined mma.sync bf16, 3-pass split -------------
// 256 threads, M-tile 128 (8 warps x 16 rows), K chunks of 64, double-buffered.
// smem (96KB): [0,32K) xh x2 | [32K,64K) xl x2 | [64K,80K) wh x2 | [80K,96K) wl x2
__global__ void __launch_bounds__(256, 2) k_gemm1_mma(const float* __restrict__ x) {
    extern __shared__ char smem[];
    const uint32_t sb = smem_to_u32(smem);

    const int tid  = threadIdx.x;
    const int warp = tid >> 5;
    const int lane = tid & 31;
    const int row0 = blockIdx.x * 128;

    float acc[8][4];
#pragma unroll
    for (int nt = 0; nt < 8; nt++)
#pragma unroll
        for (int q = 0; q < 4; q++) acc[nt][q] = 0.f;

    const int lrow = lane & 7;
    const int sub  = lane >> 3;
    const int aRowOff = lrow + (sub & 1) * 8;
    const int aColOff = (sub >> 1) * 16;
    const int bRowOff = lrow + (sub >> 1) * 8;
    const int bColOff = (sub & 1) * 16;

    const int r_ = tid >> 4;
    const int g_ = tid & 15;
    float4 xr[8];

    // prologue
    {
        uint32_t whd = sb + 65536;
        uint32_t wld = sb + 81920;
#pragma unroll
        for (int l = 0; l < 2; l++) {
            int i = tid + l * 256;
            CP_ASYNC16(whd + i * 16, g_w1h_img + i);
            CP_ASYNC16(wld + i * 16, g_w1l_img + i);
        }
        CP_COMMIT();
#pragma unroll
        for (int l = 0; l < 8; l++) {
            int r = r_ + l * 16;
            int gr = row0 + r; if (gr > NN - 1) gr = NN - 1;
            xr[l] = *(const float4*)(x + (size_t)gr * KDIM + g_ * 4);
        }
        CP_WAIT0();
    }

    for (int c = 0; c < 8; c++) {
        const int b = c & 1;
        const uint32_t bXH = sb + b * 16384;
        const uint32_t bXL = sb + 32768 + b * 16384;
        const uint32_t bWH = sb + 65536 + b * 8192;
        const uint32_t bWL = sb + 81920 + b * 8192;

#pragma unroll
        for (int l = 0; l < 8; l++) {
            int r = r_ + l * 16;
            uint2 hi, lo;
            split4(xr[l], hi, lo);
            uint32_t off = SMEM_SWIZZLE_128B((uint32_t)(r * 128 + g_ * 8));
            *(uint2*)(smem + (bXH - sb) + off) = hi;
            *(uint2*)(smem + (bXL - sb) + off) = lo;
        }
        __syncthreads();

        if (c < 7) {
            const int b2 = (c + 1) & 1;
            uint32_t whd = sb + 65536 + b2 * 8192;
            uint32_t wld = sb + 81920 + b2 * 8192;
#pragma unroll
            for (int l = 0; l < 2; l++) {
                int i = tid + l * 256;
                CP_ASYNC16(whd + i * 16, g_w1h_img + (c + 1) * 512 + i);
                CP_ASYNC16(wld + i * 16, g_w1l_img + (c + 1) * 512 + i);
            }
            CP_COMMIT();
#pragma unroll
            for (int l = 0; l < 8; l++) {
                int r = r_ + l * 16;
                int gr = row0 + r; if (gr > NN - 1) gr = NN - 1;
                xr[l] = *(const float4*)(x + (size_t)gr * KDIM + (c + 1) * 64 + g_ * 4);
            }
        }

#pragma unroll
        for (int ks = 0; ks < 4; ks++) {
            const int kb = ks * 32;
            uint32_t ah[4], al[4];
            {
                uint32_t off = SMEM_SWIZZLE_128B(
                    (uint32_t)((warp * 16 + aRowOff) * 128 + kb + aColOff));
                ldsm_x4(ah[0], ah[1], ah[2], ah[3], bXH + off);
                ldsm_x4(al[0], al[1], al[2], al[3], bXL + off);
            }
            uint32_t bh[8][2], bl[8][2];
#pragma unroll
            for (int nb = 0; nb < 4; nb++) {
                uint32_t off = SMEM_SWIZZLE_128B(
                    (uint32_t)((nb * 16 + bRowOff) * 128 + kb + bColOff));
                ldsm_x4(bh[nb * 2][0], bh[nb * 2][1], bh[nb * 2 + 1][0],
                        bh[nb * 2 + 1][1], bWH + off);
                ldsm_x4(bl[nb * 2][0], bl[nb * 2][1], bl[nb * 2 + 1][0],
                        bl[nb * 2 + 1][1], bWL + off);
            }
#pragma unroll
            for (int nt = 0; nt < 8; nt++) {
                mma_bf16(acc[nt], ah, bh[nt]);
                mma_bf16(acc[nt], al, bh[nt]);
                mma_bf16(acc[nt], ah, bl[nt]);
            }
        }
        CP_WAIT0();
    }

    const int crow = lane >> 2;
    const int ccol = (lane & 3) * 2;
    int r = row0 + warp * 16 + crow;
#pragma unroll
    for (int nt = 0; nt < 8; nt++) {
        if (r < NN)
            *(float2*)(g_xw + (size_t)r * F + nt * 8 + ccol) =
                make_float2(acc[nt][0], acc[nt][1]);
        if (r + 8 < NN)
            *(float2*)(g_xw + (size_t)(r + 8) * F + nt * 8 + ccol) =
                make_float2(acc[nt][2], acc[nt][3]);
    }
}

// ---------------- agg layer 1: warp per node, 4-way unrolled gathers -------
__global__ void k_agg1(const float* __restrict__ bias) {
    int node = (blockIdx.x * blockDim.x + threadIdx.x) >> 5;
    int lane = threadIdx.x & 31;
    if (node >= NN) return;

    int start = g_rowptr[node];
    int end   = start + g_deg[node];
    float a0 = 0.f, a1 = 0.f, b0 = 0.f, b1 = 0.f;
    float c0 = 0.f, c1 = 0.f, d0 = 0.f, d1 = 0.f;
    int j = start;
    for (; j + 3 < end; j += 4) {
        int2 e0 = __ldg(&g_edge[j]);
        int2 e1 = __ldg(&g_edge[j + 1]);
        int2 e2 = __ldg(&g_edge[j + 2]);
        int2 e3 = __ldg(&g_edge[j + 3]);
        float2 v0 = __ldg((const float2*)(g_xw + (size_t)e0.x * F) + lane);
        float2 v1 = __ldg((const float2*)(g_xw + (size_t)e1.x * F) + lane);
        float2 v2 = __ldg((const float2*)(g_xw + (size_t)e2.x * F) + lane);
        float2 v3 = __ldg((const float2*)(g_xw + (size_t)e3.x * F) + lane);
        float w0 = __int_as_float(e0.y), w1 = __int_as_float(e1.y);
        float w2 = __int_as_float(e2.y), w3 = __int_as_float(e3.y);
        a0 += w0 * v0.x; a1 += w0 * v0.y;
        b0 += w1 * v1.x; b1 += w1 * v1.y;
        c0 += w2 * v2.x; c1 += w2 * v2.y;
        d0 += w3 * v3.x; d1 += w3 * v3.y;
    }
    for (; j < end; j++) {
        int2 e0 = __ldg(&g_edge[j]);
        float2 v0 = __ldg((const float2*)(g_xw + (size_t)e0.x * F) + lane);
        float w0 = __int_as_float(e0.y);
        a0 += w0 * v0.x; a1 += w0 * v0.y;
    }
    a0 = (a0 + b0) + (c0 + d0);
    a1 = (a1 + b1) + (c1 + d1);

    float di = g_dinv[node];
    float sw = di * di;
    float2 vs = ((const float2*)(g_xw + (size_t)node * F))[lane];
    a0 += sw * vs.x;
    a1 += sw * vs.y;
    float2 bb = ((const float2*)bias)[lane];
    a0 = fmaxf(a0 + bb.x, 0.f);
    a1 = fmaxf(a1 + bb.y, 0.f);
    ((float2*)(g_h + (size_t)node * F))[lane] = make_float2(a0, a1);
}

// ---------------- fused agg2 + GEMM2 + epilogue ----------------------------
// Per block (128 thr, 64 rows): aggregate 64 nodes from g_h directly into
// bf16 hi/lo staging smem, then dual-head mma + softplus/reparam epilogue.
__global__ void __launch_bounds__(128) k_gemm2_fused(
    const float* __restrict__ bmu, const float* __restrict__ bvar,
    const float* __restrict__ eps, float* __restrict__ out) {
    __shared__ __align__(16) char s_gh[64 * 128];    // 8KB
    __shared__ __align__(16) char s_gl[64 * 128];    // 8KB
    __shared__ __align__(16) char s_wh[128 * 128];   // 16KB
    __shared__ __align__(16) char s_wl[128 * 128];   // 16KB

    const int tid  = threadIdx.x;
    const int warp = tid >> 5;
    const int lane = tid & 31;
    const int row0 = blockIdx.x * 64;

    const uint32_t bGH = smem_to_u32(s_gh);
    const uint32_t bGL = smem_to_u32(s_gl);
    const uint32_t bWH = smem_to_u32(s_wh);
    const uint32_t bWL = smem_to_u32(s_wl);

    // W images copy (no dependency on agg phase)
    {
        uint4* dH = (uint4*)s_wh;
        uint4* dL = (uint4*)s_wl;
#pragma unroll
        for (int l = 0; l < 8; l++) {
            int i = tid + l * 128;
            dH[i] = g_w2h_img[i];
            dL[i] = g_w2l_img[i];
        }
    }

    // ---- phase A: aggregate this tile's 64 nodes (warp-per-node x16) ----
    for (int i = 0; i < 16; i++) {
        int r    = warp * 16 + i;          // tile row
        int node = row0 + r;
        float a0 = 0.f, a1 = 0.f;
        if (node < NN) {
            int start = g_rowptr[node];
            int end   = start + g_deg[node];
            float b0 = 0.f, b1 = 0.f, c0 = 0.f, c1 = 0.f, d0 = 0.f, d1 = 0.f;
            int j = start;
            for (; j + 3 < end; j += 4) {
                int2 e0 = __ldg(&g_edge[j]);
                int2 e1 = __ldg(&g_edge[j + 1]);
                int2 e2 = __ldg(&g_edge[j + 2]);
                int2 e3 = __ldg(&g_edge[j + 3]);
                float2 v0 = __ldg((const float2*)(g_h + (size_t)e0.x * F) + lane);
                float2 v1 = __ldg((const float2*)(g_h + (size_t)e1.x * F) + lane);
                float2 v2 = __ldg((const float2*)(g_h + (size_t)e2.x * F) + lane);
                float2 v3 = __ldg((const float2*)(g_h + (size_t)e3.x * F) + lane);
                float w0 = __int_as_float(e0.y), w1 = __int_as_float(e1.y);
                float w2 = __int_as_float(e2.y), w3 = __int_as_float(e3.y);
                a0 += w0 * v0.x; a1 += w0 * v0.y;
                b0 += w1 * v1.x; b1 += w1 * v1.y;
                c0 += w2 * v2.x; c1 += w2 * v2.y;
                d0 += w3 * v3.x; d1 += w3 * v3.y;
            }
            for (; j < end; j++) {
                int2 e0 = __ldg(&g_edge[j]);
                float2 v0 = __ldg((const float2*)(g_h + (size_t)e0.x * F) + lane);
                float w0 = __int_as_float(e0.y);
                a0 += w0 * v0.x; a1 += w0 * v0.y;
            }
            a0 = (a0 + b0) + (c0 + d0);
            a1 = (a1 + b1) + (c1 + d1);
            float di = g_dinv[node];
            float sw = di * di;
            float2 vs = ((const float2*)(g_h + (size_t)node * F))[lane];
            a0 += sw * vs.x;
            a1 += sw * vs.y;
        }
        // split to bf16 hi/lo and store into ldsm staging layout
        uint32_t ua = __float_as_uint(a0), ub = __float_as_uint(a1);
        uint32_t hip = __byte_perm(ua, ub, 0x7632);
        float r0 = a0 - __uint_as_float(ua & 0xFFFF0000u);
        float r1 = a1 - __uint_as_float(ub & 0xFFFF0000u);
        uint32_t lop = cvt_bf16x2(r1, r0);
        uint32_t off = SMEM_SWIZZLE_128B((uint32_t)(r * 128 + lane * 4));
        *(uint32_t*)(s_gh + off) = hip;
        *(uint32_t*)(s_gl + off) = lop;
    }
    __syncthreads();

    // ---- phase B: dual-head mma ----
    float acc[16][4];
#pragma unroll
    for (int nt = 0; nt < 16; nt++)
#pragma unroll
        for (int q = 0; q < 4; q++) acc[nt][q] = 0.f;

    const int lrow = lane & 7;
    const int sub  = lane >> 3;
    const int aRowOff = lrow + (sub & 1) * 8;
    const int aColOff = (sub >> 1) * 16;
    const int bRowOff = lrow + (sub >> 1) * 8;
    const int bColOff = (sub & 1) * 16;

#pragma unroll
    for (int ks = 0; ks < 4; ks++) {
        const int kb = ks * 32;
        uint32_t ah[4], al[4];
        {
            uint32_t off = SMEM_SWIZZLE_128B(
                (uint32_t)((warp * 16 + aRowOff) * 128 + kb + aColOff));
            ldsm_x4(ah[0], ah[1], ah[2], ah[3], bGH + off);
            ldsm_x4(al[0], al[1], al[2], al[3], bGL + off);
        }
#pragma unroll
        for (int nb = 0; nb < 8; nb++) {
            uint32_t off = SMEM_SWIZZLE_128B(
                (uint32_t)((nb * 16 + bRowOff) * 128 + kb + bColOff));
            uint32_t h0, h1, h2, h3, l0, l1, l2, l3;
            ldsm_x4(h0, h1, h2, h3, bWH + off);
            ldsm_x4(l0, l1, l2, l3, bWL + off);
            uint32_t bhA[2] = {h0, h1}, bhB[2] = {h2, h3};
            uint32_t blA[2] = {l0, l1}, blB[2] = {l2, l3};
            mma_bf16(acc[nb * 2],     ah, bhA);
            mma_bf16(acc[nb * 2],     al, bhA);
            mma_bf16(acc[nb * 2],     ah, blA);
            mma_bf16(acc[nb * 2 + 1], ah, bhB);
            mma_bf16(acc[nb * 2 + 1], al, bhB);
            mma_bf16(acc[nb * 2 + 1], ah, blB);
        }
    }

    // ---- epilogue: mu (nt<8) pairs with var (nt+8) in the same thread ----
    const int crow  = lane >> 2;
    const int ccol  = (lane & 3) * 2;
    const size_t secz = (size_t)NN * F;
#pragma unroll
    for (int half = 0; half < 2; half++) {
        int r = row0 + warp * 16 + crow + half * 8;
        if (r >= NN) continue;
#pragma unroll
        for (int nt = 0; nt < 8; nt++) {
            int col = nt * 8 + ccol;
            float mu0 = acc[nt][half * 2 + 0]     + bmu[col];
            float mu1 = acc[nt][half * 2 + 1]     + bmu[col + 1];
            float vl0 = acc[nt + 8][half * 2 + 0] + bvar[col];
            float vl1 = acc[nt + 8][half * 2 + 1] + bvar[col + 1];
            float sp0 = fmaxf(vl0, 0.f) + log1pf(expf(-fabsf(vl0)));
            float sp1 = fmaxf(vl1, 0.f) + log1pf(expf(-fabsf(vl1)));
            float2 e  = *(const float2*)(eps + (size_t)r * F + col);
            size_t off = (size_t)r * F + col;
            *(float2*)(out + off)            = make_float2(mu0, mu1);
            *(float2*)(out + secz + off)     = make_float2(sp0, sp1);
            *(float2*)(out + 2 * secz + off) = make_float2(mu0 + sp0 * e.x,
                                                           mu1 + sp1 * e.y);
        }
    }
}

// ---------------- launch ---------------------------------------------------
extern "C" void kernel_launch(void* const* d_in, const int* in_sizes, int n_in,
                              void* d_out, int out_size) {
    const float* x    = (const float*)d_in[0];
    const int*   ei   = (const int*)d_in[1];    // edge_index is int32
    const float* W1   = (const float*)d_in[2];
    const float* b1   = (const float*)d_in[3];
    const float* Wmu  = (const float*)d_in[4];
    const float* bmu  = (const float*)d_in[5];
    const float* Wvar = (const float*)d_in[6];
    const float* bvar = (const float*)d_in[7];
    const float* eps  = (const float*)d_in[8];
    float*       out  = (float*)d_out;

    cudaFuncSetAttribute(k_gemm1_mma,
                         cudaFuncAttributeMaxDynamicSharedMemorySize, 98304);

    // prep: zero deg/cursor + pre-split both weight sets (one launch)
    k_prep<<<411, 256>>>(W1, Wmu, Wvar);

    // CSR build
    k_hist       <<<(NE + 255) / 256, 256>>>(ei);
    k_scan_local <<<NB, 1024>>>();
    k_scan_finish<<<NB, 1024>>>();
    k_scatter    <<<(NE + 255) / 256, 256>>>(ei);

    // layer 1: pipelined tensor-core GEMM then aggregate (+bias, relu)
    k_gemm1_mma<<<(NN + 127) / 128, 256, 98304>>>(x);
    k_agg1     <<<(NN + 7) / 8, 256>>>(b1);

    // layer 2: fused aggregate + dual-head GEMM + epilogue
    k_gemm2_fused<<<(NN + 63) / 64, 128>>>(bmu, bvar, eps, out);
}

// round 12
// speedup vs baseline: 1.2398x; 1.2398x over previous
#include <cuda_runtime.h>
#include <cuda_bf16.h>
#include <stdint.h>
#include <math.h>

#define NN 100000
#define NE 1600000
#define KDIM 512
#define F 64
#define NB 98        // ceil(NN/1024)

// ---------------- scratch (device globals; no allocation allowed) ----------
__device__ __align__(16) int   g_deg[NN];
__device__ __align__(16) float g_dinv[NN];
__device__ __align__(16) int   g_rowptr[NN];
__device__ __align__(16) int   g_cursor[NN];
__device__ __align__(16) int   g_blocksums[128];
__device__ __align__(16) int2  g_edge[NE];             // {src, weight bits}
__device__ __align__(16) float g_xw[(size_t)NN * F];   // x @ W1
__device__ __align__(16) float g_h [(size_t)NN * F];   // relu(Agg(xw)+b1)
__device__ __align__(16) float g_g [(size_t)NN * F];   // Agg(h)
// pre-split, pre-swizzled weight images (smem-ready)
__device__ __align__(16) uint4 g_w1h_img[4096];        // 8 chunks x 8KB
__device__ __align__(16) uint4 g_w1l_img[4096];
__device__ __align__(16) uint4 g_w2h_img[1024];        // 16KB: [Wmu|Wvar]^T
__device__ __align__(16) uint4 g_w2l_img[1024];

#define SMEM_SWIZZLE_128B(off) ((off) ^ (((off) >> 3) & 0x70))

__device__ __forceinline__ uint32_t smem_to_u32(const void* p) {
    uint32_t a;
    asm("{ .reg .u64 t; cvta.to.shared.u64 t, %1; cvt.u32.u64 %0, t; }"
        : "=r"(a) : "l"(p));
    return a;
}
__device__ __forceinline__ uint32_t pack_bf16x2(__nv_bfloat16 lo, __nv_bfloat16 hi) {
    __nv_bfloat162 t; t.x = lo; t.y = hi;
    return *reinterpret_cast<uint32_t*>(&t);
}
__device__ __forceinline__ uint32_t cvt_bf16x2(float hi, float lo) {
    uint32_t r;
    asm("cvt.rn.bf16x2.f32 %0, %1, %2;" : "=r"(r) : "f"(hi), "f"(lo));
    return r;
}
__device__ __forceinline__ void ldsm_x4(uint32_t& r0, uint32_t& r1, uint32_t& r2,
                                        uint32_t& r3, uint32_t addr) {
    asm volatile("ldmatrix.sync.aligned.m8n8.x4.shared.b16 {%0,%1,%2,%3}, [%4];"
                 : "=r"(r0), "=r"(r1), "=r"(r2), "=r"(r3) : "r"(addr));
}
__device__ __forceinline__ void mma_bf16(float* c, const uint32_t* a,
                                         const uint32_t* b) {
    asm volatile(
        "mma.sync.aligned.m16n8k16.row.col.f32.bf16.bf16.f32 "
        "{%0,%1,%2,%3}, {%4,%5,%6,%7}, {%8,%9}, {%0,%1,%2,%3};"
        : "+f"(c[0]), "+f"(c[1]), "+f"(c[2]), "+f"(c[3])
        : "r"(a[0]), "r"(a[1]), "r"(a[2]), "r"(a[3]), "r"(b[0]), "r"(b[1]));
}
__device__ __forceinline__ void split4(float4 v, uint2& hi, uint2& lo) {
    uint32_t ax = __float_as_uint(v.x), ay = __float_as_uint(v.y);
    uint32_t az = __float_as_uint(v.z), aw = __float_as_uint(v.w);
    hi.x = __byte_perm(ax, ay, 0x7632);
    hi.y = __byte_perm(az, aw, 0x7632);
    float rx = v.x - __uint_as_float(ax & 0xFFFF0000u);
    float ry = v.y - __uint_as_float(ay & 0xFFFF0000u);
    float rz = v.z - __uint_as_float(az & 0xFFFF0000u);
    float rw = v.w - __uint_as_float(aw & 0xFFFF0000u);
    lo.x = cvt_bf16x2(ry, rx);
    lo.y = cvt_bf16x2(rw, rz);
}
#define CP_ASYNC16(dst, src) \
    asm volatile("cp.async.cg.shared.global [%0], [%1], 16;" \
                 :: "r"(dst), "l"(src) : "memory")
#define CP_COMMIT() asm volatile("cp.async.commit_group;" ::: "memory")
#define CP_WAIT0()  asm volatile("cp.async.wait_group 0;" ::: "memory")

// ---------------- prep: zero ∥ splitW1 ∥ splitW2 (one launch) --------------
__global__ void __launch_bounds__(256) k_prep(const float* __restrict__ W1,
                                              const float* __restrict__ Wmu,
                                              const float* __restrict__ Wvar) {
    int bx = blockIdx.x;
    int tid = threadIdx.x;
    if (bx < 391) {                       // zero deg/cursor
        int i = bx * 256 + tid;
        if (i < NN) { g_deg[i] = 0; g_cursor[i] = 0; }
    } else if (bx < 407) {                // splitW1: 4096 granules
        int gid = (bx - 391) * 256 + tid;
        int c  = gid >> 9;
        int g  = gid & 511;
        int n  = g >> 3;
        int k8 = (g & 7) * 8;
        uint32_t hi[4], lo[4];
#pragma unroll
        for (int jj = 0; jj < 4; jj++) {
            float w0 = W1[(size_t)(c * 64 + k8 + jj * 2 + 0) * F + n];
            float w1 = W1[(size_t)(c * 64 + k8 + jj * 2 + 1) * F + n];
            __nv_bfloat16 a0 = __float2bfloat16(w0), a1 = __float2bfloat16(w1);
            __nv_bfloat16 b0 = __float2bfloat16(w0 - __bfloat162float(a0));
            __nv_bfloat16 b1 = __float2bfloat16(w1 - __bfloat162float(a1));
            hi[jj] = pack_bf16x2(a0, a1);
            lo[jj] = pack_bf16x2(b0, b1);
        }
        uint32_t off = SMEM_SWIZZLE_128B((uint32_t)(n * 128 + k8 * 2)) >> 4;
        g_w1h_img[c * 512 + off] = make_uint4(hi[0], hi[1], hi[2], hi[3]);
        g_w1l_img[c * 512 + off] = make_uint4(lo[0], lo[1], lo[2], lo[3]);
    } else {                              // splitW2: 1024 granules
        int gid = (bx - 407) * 256 + tid;
        int n  = gid >> 3;
        int k8 = (gid & 7) * 8;
        const float* Wsrc = (n < 64) ? Wmu : Wvar;
        int nn = n & 63;
        uint32_t hi[4], lo[4];
#pragma unroll
        for (int jj = 0; jj < 4; jj++) {
            float w0 = Wsrc[(size_t)(k8 + jj * 2 + 0) * 64 + nn];
            float w1 = Wsrc[(size_t)(k8 + jj * 2 + 1) * 64 + nn];
            __nv_bfloat16 a0 = __float2bfloat16(w0), a1 = __float2bfloat16(w1);
            __nv_bfloat16 b0 = __float2bfloat16(w0 - __bfloat162float(a0));
            __nv_bfloat16 b1 = __float2bfloat16(w1 - __bfloat162float(a1));
            hi[jj] = pack_bf16x2(a0, a1);
            lo[jj] = pack_bf16x2(b0, b1);
        }
        uint32_t off = SMEM_SWIZZLE_128B((uint32_t)(n * 128 + k8 * 2)) >> 4;
        g_w2h_img[off] = make_uint4(hi[0], hi[1], hi[2], hi[3]);
        g_w2l_img[off] = make_uint4(lo[0], lo[1], lo[2], lo[3]);
    }
}

// ---------------- CSR build ------------------------------------------------
__global__ void k_hist(const int* __restrict__ ei) {
    int e = blockIdx.x * blockDim.x + threadIdx.x;
    if (e < NE) atomicAdd(&g_deg[ei[NE + e]], 1);
}
__global__ void k_scan_local() {
    __shared__ int s[1024];
    int t = threadIdx.x;
    int i = blockIdx.x * 1024 + t;
    int v = (i < NN) ? g_deg[i] : 0;
    if (i < NN) g_dinv[i] = rsqrtf((float)v + 1.0f);
    s[t] = v; __syncthreads();
    for (int off = 1; off < 1024; off <<= 1) {
        int x = (t >= off) ? s[t - off] : 0;
        __syncthreads();
        s[t] += x;
        __syncthreads();
    }
    if (i < NN) g_rowptr[i] = s[t] - v;
    if (t == 1023) g_blocksums[blockIdx.x] = s[1023];
}
__global__ void k_scan_finish() {
    __shared__ int s[128];
    __shared__ int s_off;
    int t  = threadIdx.x;
    int bx = blockIdx.x;
    if (t < NB) s[t] = g_blocksums[t];
    __syncthreads();
    if (t == 0) {
        int acc = 0;
        for (int k = 0; k < bx; k++) acc += s[k];
        s_off = acc;
    }
    __syncthreads();
    int i = bx * 1024 + t;
    if (i < NN) g_rowptr[i] += s_off;
}
__global__ void k_scatter(const int* __restrict__ ei) {
    int e = blockIdx.x * blockDim.x + threadIdx.x;
    if (e >= NE) return;
    int src = ei[e];
    int dst = ei[NE + e];
    int pos = g_rowptr[dst] + atomicAdd(&g_cursor[dst], 1);
    g_edge[pos] = make_int2(src, __float_as_int(g_dinv[src] * g_dinv[dst]));
}

// ---------------- GEMM1: pipelined mma.sync bf16, 3-pass split -------------
// 256 threads, M-tile 128 (8 warps x 16 rows), K chunks of 64, double-buffered.
// smem (96KB): [0,32K) xh x2 | [32K,64K) xl x2 | [64K,80K) wh x2 | [80K,96K) wl x2
__global__ void __launch_bounds__(256, 2) k_gemm1_mma(const float* __restrict__ x) {
    extern __shared__ char smem[];
    const uint32_t sb = smem_to_u32(smem);

    const int tid  = threadIdx.x;
    const int warp = tid >> 5;
    const int lane = tid & 31;
    const int row0 = blockIdx.x * 128;

    float acc[8][4];
#pragma unroll
    for (int nt = 0; nt < 8; nt++)
#pragma unroll
        for (int q = 0; q < 4; q++) acc[nt][q] = 0.f;

    const int lrow = lane & 7;
    const int sub  = lane >> 3;
    const int aRowOff = lrow + (sub & 1) * 8;
    const int aColOff = (sub >> 1) * 16;
    const int bRowOff = lrow + (sub >> 1) * 8;
    const int bColOff = (sub & 1) * 16;

    const int r_ = tid >> 4;
    const int g_ = tid & 15;
    float4 xr[8];

    // prologue
    {
        uint32_t whd = sb + 65536;
        uint32_t wld = sb + 81920;
#pragma unroll
        for (int l = 0; l < 2; l++) {
            int i = tid + l * 256;
            CP_ASYNC16(whd + i * 16, g_w1h_img + i);
            CP_ASYNC16(wld + i * 16, g_w1l_img + i);
        }
        CP_COMMIT();
#pragma unroll
        for (int l = 0; l < 8; l++) {
            int r = r_ + l * 16;
            int gr = row0 + r; if (gr > NN - 1) gr = NN - 1;
            xr[l] = *(const float4*)(x + (size_t)gr * KDIM + g_ * 4);
        }
        CP_WAIT0();
    }

    for (int c = 0; c < 8; c++) {
        const int b = c & 1;
        const uint32_t bXH = sb + b * 16384;
        const uint32_t bXL = sb + 32768 + b * 16384;
        const uint32_t bWH = sb + 65536 + b * 8192;
        const uint32_t bWL = sb + 81920 + b * 8192;

#pragma unroll
        for (int l = 0; l < 8; l++) {
            int r = r_ + l * 16;
            uint2 hi, lo;
            split4(xr[l], hi, lo);
            uint32_t off = SMEM_SWIZZLE_128B((uint32_t)(r * 128 + g_ * 8));
            *(uint2*)(smem + (bXH - sb) + off) = hi;
            *(uint2*)(smem + (bXL - sb) + off) = lo;
        }
        __syncthreads();

        if (c < 7) {
            const int b2 = (c + 1) & 1;
            uint32_t whd = sb + 65536 + b2 * 8192;
            uint32_t wld = sb + 81920 + b2 * 8192;
#pragma unroll
            for (int l = 0; l < 2; l++) {
                int i = tid + l * 256;
                CP_ASYNC16(whd + i * 16, g_w1h_img + (c + 1) * 512 + i);
                CP_ASYNC16(wld + i * 16, g_w1l_img + (c + 1) * 512 + i);
            }
            CP_COMMIT();
#pragma unroll
            for (int l = 0; l < 8; l++) {
                int r = r_ + l * 16;
                int gr = row0 + r; if (gr > NN - 1) gr = NN - 1;
                xr[l] = *(const float4*)(x + (size_t)gr * KDIM + (c + 1) * 64 + g_ * 4);
            }
        }

#pragma unroll
        for (int ks = 0; ks < 4; ks++) {
            const int kb = ks * 32;
            uint32_t ah[4], al[4];
            {
                uint32_t off = SMEM_SWIZZLE_128B(
                    (uint32_t)((warp * 16 + aRowOff) * 128 + kb + aColOff));
                ldsm_x4(ah[0], ah[1], ah[2], ah[3], bXH + off);
                ldsm_x4(al[0], al[1], al[2], al[3], bXL + off);
            }
            uint32_t bh[8][2], bl[8][2];
#pragma unroll
            for (int nb = 0; nb < 4; nb++) {
                uint32_t off = SMEM_SWIZZLE_128B(
                    (uint32_t)((nb * 16 + bRowOff) * 128 + kb + bColOff));
                ldsm_x4(bh[nb * 2][0], bh[nb * 2][1], bh[nb * 2 + 1][0],
                        bh[nb * 2 + 1][1], bWH + off);
                ldsm_x4(bl[nb * 2][0], bl[nb * 2][1], bl[nb * 2 + 1][0],
                        bl[nb * 2 + 1][1], bWL + off);
            }
#pragma unroll
            for (int nt = 0; nt < 8; nt++) {
                mma_bf16(acc[nt], ah, bh[nt]);
                mma_bf16(acc[nt], al, bh[nt]);
                mma_bf16(acc[nt], ah, bl[nt]);
            }
        }
        CP_WAIT0();
    }

    const int crow = lane >> 2;
    const int ccol = (lane & 3) * 2;
    int r = row0 + warp * 16 + crow;
#pragma unroll
    for (int nt = 0; nt < 8; nt++) {
        if (r < NN)
            *(float2*)(g_xw + (size_t)r * F + nt * 8 + ccol) =
                make_float2(acc[nt][0], acc[nt][1]);
        if (r + 8 < NN)
            *(float2*)(g_xw + (size_t)(r + 8) * F + nt * 8 + ccol) =
                make_float2(acc[nt][2], acc[nt][3]);
    }
}

// ---------------- aggregation: warp per node, 4-way unrolled gathers -------
__global__ void k_agg(const float* __restrict__ bias, int layer) {
    int node = (blockIdx.x * blockDim.x + threadIdx.x) >> 5;
    int lane = threadIdx.x & 31;
    if (node >= NN) return;
    const float* fin = (layer == 1) ? g_xw : g_h;
    float*       fout = (layer == 1) ? g_h : g_g;

    int start = g_rowptr[node];
    int end   = start + g_deg[node];
    float a0 = 0.f, a1 = 0.f, b0 = 0.f, b1 = 0.f;
    float c0 = 0.f, c1 = 0.f, d0 = 0.f, d1 = 0.f;
    int j = start;
    for (; j + 3 < end; j += 4) {
        int2 e0 = __ldg(&g_edge[j]);
        int2 e1 = __ldg(&g_edge[j + 1]);
        int2 e2 = __ldg(&g_edge[j + 2]);
        int2 e3 = __ldg(&g_edge[j + 3]);
        float2 v0 = __ldg((const float2*)(fin + (size_t)e0.x * F) + lane);
        float2 v1 = __ldg((const float2*)(fin + (size_t)e1.x * F) + lane);
        float2 v2 = __ldg((const float2*)(fin + (size_t)e2.x * F) + lane);
        float2 v3 = __ldg((const float2*)(fin + (size_t)e3.x * F) + lane);
        float w0 = __int_as_float(e0.y), w1 = __int_as_float(e1.y);
        float w2 = __int_as_float(e2.y), w3 = __int_as_float(e3.y);
        a0 += w0 * v0.x; a1 += w0 * v0.y;
        b0 += w1 * v1.x; b1 += w1 * v1.y;
        c0 += w2 * v2.x; c1 += w2 * v2.y;
        d0 += w3 * v3.x; d1 += w3 * v3.y;
    }
    for (; j < end; j++) {
        int2 e0 = __ldg(&g_edge[j]);
        float2 v0 = __ldg((const float2*)(fin + (size_t)e0.x * F) + lane);
        float w0 = __int_as_float(e0.y);
        a0 += w0 * v0.x; a1 += w0 * v0.y;
    }
    a0 = (a0 + b0) + (c0 + d0);
    a1 = (a1 + b1) + (c1 + d1);

    float di = g_dinv[node];
    float sw = di * di;
    float2 vs = ((const float2*)(fin + (size_t)node * F))[lane];
    a0 += sw * vs.x;
    a1 += sw * vs.y;
    if (layer == 1) {
        float2 bb = ((const float2*)bias)[lane];
        a0 = fmaxf(a0 + bb.x, 0.f);
        a1 = fmaxf(a1 + bb.y, 0.f);
    }
    ((float2*)(fout + (size_t)node * F))[lane] = make_float2(a0, a1);
}

// ---------------- GEMM2 via mma.sync bf16, 3-pass split + epilogue ---------
__global__ void __launch_bounds__(128) k_gemm2_mma(
    const float* __restrict__ bmu, const float* __restrict__ bvar,
    const float* __restrict__ eps, float* __restrict__ out) {
    __shared__ __align__(16) char s_gh[64 * 128];
    __shared__ __align__(16) char s_gl[64 * 128];
    __shared__ __align__(16) char s_wh[128 * 128];
    __shared__ __align__(16) char s_wl[128 * 128];

    const int tid  = threadIdx.x;
    const int warp = tid >> 5;
    const int lane = tid & 31;
    const int row0 = blockIdx.x * 64;

    const uint32_t bGH = smem_to_u32(s_gh);
    const uint32_t bGL = smem_to_u32(s_gl);
    const uint32_t bWH = smem_to_u32(s_wh);
    const uint32_t bWL = smem_to_u32(s_wl);

#pragma unroll
    for (int l = 0; l < 8; l++) {
        int idx = tid + l * 128;
        int g   = idx & 15;
        int r   = idx >> 4;
        int gr  = row0 + r; if (gr > NN - 1) gr = NN - 1;
        float4 v = *(const float4*)(g_g + (size_t)gr * F + g * 4);
        uint2 hi, lo;
        split4(v, hi, lo);
        uint32_t off = SMEM_SWIZZLE_128B((uint32_t)(r * 128 + g * 8));
        *(uint2*)(s_gh + off) = hi;
        *(uint2*)(s_gl + off) = lo;
    }
    {
        uint4* dH = (uint4*)s_wh;
        uint4* dL = (uint4*)s_wl;
#pragma unroll
        for (int l = 0; l < 8; l++) {
            int i = tid + l * 128;
            dH[i] = g_w2h_img[i];
            dL[i] = g_w2l_img[i];
        }
    }
    __syncthreads();

    float acc[16][4];
#pragma unroll
    for (int nt = 0; nt < 16; nt++)
#pragma unroll
        for (int q = 0; q < 4; q++) acc[nt][q] = 0.f;

    const int lrow = lane & 7;
    const int sub  = lane >> 3;
    const int aRowOff = lrow + (sub & 1) * 8;
    const int aColOff = (sub >> 1) * 16;
    const int bRowOff = lrow + (sub >> 1) * 8;
    const int bColOff = (sub & 1) * 16;

#pragma unroll
    for (int ks = 0; ks < 4; ks++) {
        const int kb = ks * 32;
        uint32_t ah[4], al[4];
        {
            uint32_t off = SMEM_SWIZZLE_128B(
                (uint32_t)((warp * 16 + aRowOff) * 128 + kb + aColOff));
            ldsm_x4(ah[0], ah[1], ah[2], ah[3], bGH + off);
            ldsm_x4(al[0], al[1], al[2], al[3], bGL + off);
        }
#pragma unroll
        for (int nb = 0; nb < 8; nb++) {
            uint32_t off = SMEM_SWIZZLE_128B(
                (uint32_t)((nb * 16 + bRowOff) * 128 + kb + bColOff));
            uint32_t h0, h1, h2, h3, l0, l1, l2, l3;
            ldsm_x4(h0, h1, h2, h3, bWH + off);
            ldsm_x4(l0, l1, l2, l3, bWL + off);
            uint32_t bhA[2] = {h0, h1}, bhB[2] = {h2, h3};
            uint32_t blA[2] = {l0, l1}, blB[2] = {l2, l3};
            mma_bf16(acc[nb * 2],     ah, bhA);
            mma_bf16(acc[nb * 2],     al, bhA);
            mma_bf16(acc[nb * 2],     ah, blA);
            mma_bf16(acc[nb * 2 + 1], ah, bhB);
            mma_bf16(acc[nb * 2 + 1], al, bhB);
            mma_bf16(acc[nb * 2 + 1], ah, blB);
        }
    }

    const int crow  = lane >> 2;
    const int ccol  = (lane & 3) * 2;
    const size_t secz = (size_t)NN * F;
#pragma unroll
    for (int half = 0; half < 2; half++) {
        int r = row0 + warp * 16 + crow + half * 8;
        if (r >= NN) continue;
#pragma unroll
        for (int nt = 0; nt < 8; nt++) {
            int col = nt * 8 + ccol;
            float mu0 = acc[nt][half * 2 + 0]     + bmu[col];
            float mu1 = acc[nt][half * 2 + 1]     + bmu[col + 1];
            float vl0 = acc[nt + 8][half * 2 + 0] + bvar[col];
            float vl1 = acc[nt + 8][half * 2 + 1] + bvar[col + 1];
            float sp0 = fmaxf(vl0, 0.f) + log1pf(expf(-fabsf(vl0)));
            float sp1 = fmaxf(vl1, 0.f) + log1pf(expf(-fabsf(vl1)));
            float2 e  = *(const float2*)(eps + (size_t)r * F + col);
            size_t off = (size_t)r * F + col;
            *(float2*)(out + off)            = make_float2(mu0, mu1);
            *(float2*)(out + secz + off)     = make_float2(sp0, sp1);
            *(float2*)(out + 2 * secz + off) = make_float2(mu0 + sp0 * e.x,
                                                           mu1 + sp1 * e.y);
        }
    }
}

// ---------------- launch ---------------------------------------------------
extern "C" void kernel_launch(void* const* d_in, const int* in_sizes, int n_in,
                              void* d_out, int out_size) {
    const float* x    = (const float*)d_in[0];
    const int*   ei   = (const int*)d_in[1];    // edge_index is int32
    const float* W1   = (const float*)d_in[2];
    const float* b1   = (const float*)d_in[3];
    const float* Wmu  = (const float*)d_in[4];
    const float* bmu  = (const float*)d_in[5];
    const float* Wvar = (const float*)d_in[6];
    const float* bvar = (const float*)d_in[7];
    const float* eps  = (const float*)d_in[8];
    float*       out  = (float*)d_out;

    cudaFuncSetAttribute(k_gemm1_mma,
                         cudaFuncAttributeMaxDynamicSharedMemorySize, 98304);

    // prep: zero deg/cursor + pre-split both weight sets (one launch)
    k_prep<<<411, 256>>>(W1, Wmu, Wvar);

    // CSR build
    k_hist       <<<(NE + 255) / 256, 256>>>(ei);
    k_scan_local <<<NB, 1024>>>();
    k_scan_finish<<<NB, 1024>>>();
    k_scatter    <<<(NE + 255) / 256, 256>>>(ei);

    // layer 1: pipelined tensor-core GEMM then aggregate (+bias, relu)
    k_gemm1_mma<<<(NN + 127) / 128, 256, 98304>>>(x);
    k_agg      <<<(NN + 7) / 8, 256>>>(b1, 1);

    // layer 2: aggregate first (linearity), then fused dual-head GEMM + epilogue
    k_agg      <<<(NN + 7) / 8, 256>>>(nullptr, 2);
    k_gemm2_mma<<<(NN + 63) / 64, 128>>>(bmu, bvar, eps, out);
}

// round 14
// speedup vs baseline: 1.3467x; 1.0862x over previous
#include <cuda_runtime.h>
#include <cuda_bf16.h>
#include <stdint.h>
#include <math.h>

#define NN 100000
#define NE 1600000
#define KDIM 512
#define F 64
#define NB 98        // ceil(NN/1024)

// ---------------- scratch (device globals; no allocation allowed) ----------
__device__ __align__(16) int   g_deg[NN];
__device__ __align__(16) float g_dinv[NN];
__device__ __align__(16) int   g_rowptr[NN];
__device__ __align__(16) int   g_cursor[NN];
__device__ __align__(16) int   g_blocksums[128];
__device__ __align__(16) int2  g_edge[NE];             // {src, weight bits}
__device__ __align__(16) float g_xw[(size_t)NN * F];   // x @ W1
__device__ __align__(16) float g_h [(size_t)NN * F];   // relu(Agg(xw)+b1)
__device__ __align__(16) float g_g [(size_t)NN * F];   // Agg(h)
// pre-split, pre-swizzled weight images (smem-ready)
__device__ __align__(16) uint4 g_w1h_img[4096];        // 8 chunks x 8KB
__device__ __align__(16) uint4 g_w1l_img[4096];
__device__ __align__(16) uint4 g_w2h_img[1024];        // 16KB: [Wmu|Wvar]^T
__device__ __align__(16) uint4 g_w2l_img[1024];

#define SMEM_SWIZZLE_128B(off) ((off) ^ (((off) >> 3) & 0x70))

__device__ __forceinline__ uint32_t smem_to_u32(const void* p) {
    uint32_t a;
    asm("{ .reg .u64 t; cvta.to.shared.u64 t, %1; cvt.u32.u64 %0, t; }"
        : "=r"(a) : "l"(p));
    return a;
}
__device__ __forceinline__ uint32_t pack_bf16x2(__nv_bfloat16 lo, __nv_bfloat16 hi) {
    __nv_bfloat162 t; t.x = lo; t.y = hi;
    return *reinterpret_cast<uint32_t*>(&t);
}
__device__ __forceinline__ uint32_t cvt_bf16x2(float hi, float lo) {
    uint32_t r;
    asm("cvt.rn.bf16x2.f32 %0, %1, %2;" : "=r"(r) : "f"(hi), "f"(lo));
    return r;
}
__device__ __forceinline__ void ldsm_x4(uint32_t& r0, uint32_t& r1, uint32_t& r2,
                                        uint32_t& r3, uint32_t addr) {
    asm volatile("ldmatrix.sync.aligned.m8n8.x4.shared.b16 {%0,%1,%2,%3}, [%4];"
                 : "=r"(r0), "=r"(r1), "=r"(r2), "=r"(r3) : "r"(addr));
}
__device__ __forceinline__ void mma_bf16(float* c, const uint32_t* a,
                                         const uint32_t* b) {
    asm volatile(
        "mma.sync.aligned.m16n8k16.row.col.f32.bf16.bf16.f32 "
        "{%0,%1,%2,%3}, {%4,%5,%6,%7}, {%8,%9}, {%0,%1,%2,%3};"
        : "+f"(c[0]), "+f"(c[1]), "+f"(c[2]), "+f"(c[3])
        : "r"(a[0]), "r"(a[1]), "r"(a[2]), "r"(a[3]), "r"(b[0]), "r"(b[1]));
}
__device__ __forceinline__ void split4(float4 v, uint2& hi, uint2& lo) {
    uint32_t ax = __float_as_uint(v.x), ay = __float_as_uint(v.y);
    uint32_t az = __float_as_uint(v.z), aw = __float_as_uint(v.w);
    hi.x = __byte_perm(ax, ay, 0x7632);
    hi.y = __byte_perm(az, aw, 0x7632);
    float rx = v.x - __uint_as_float(ax & 0xFFFF0000u);
    float ry = v.y - __uint_as_float(ay & 0xFFFF0000u);
    float rz = v.z - __uint_as_float(az & 0xFFFF0000u);
    float rw = v.w - __uint_as_float(aw & 0xFFFF0000u);
    lo.x = cvt_bf16x2(ry, rx);
    lo.y = cvt_bf16x2(rw, rz);
}
#define CP_ASYNC16(dst, src) \
    asm volatile("cp.async.cg.shared.global [%0], [%1], 16;" \
                 :: "r"(dst), "l"(src) : "memory")
#define CP_COMMIT() asm volatile("cp.async.commit_group;" ::: "memory")
#define CP_WAIT0()  asm volatile("cp.async.wait_group 0;" ::: "memory")

// ---------------- prep: zero ∥ splitW1 ∥ splitW2 (one launch) --------------
__global__ void __launch_bounds__(256) k_prep(const float* __restrict__ W1,
                                              const float* __restrict__ Wmu,
                                              const float* __restrict__ Wvar) {
    int bx = blockIdx.x;
    int tid = threadIdx.x;
    if (bx < 391) {                       // zero deg/cursor
        int i = bx * 256 + tid;
        if (i < NN) { g_deg[i] = 0; g_cursor[i] = 0; }
    } else if (bx < 407) {                // splitW1: 4096 granules
        int gid = (bx - 391) * 256 + tid;
        int c  = gid >> 9;
        int g  = gid & 511;
        int n  = g >> 3;
        int k8 = (g & 7) * 8;
        uint32_t hi[4], lo[4];
#pragma unroll
        for (int jj = 0; jj < 4; jj++) {
            float w0 = W1[(size_t)(c * 64 + k8 + jj * 2 + 0) * F + n];
            float w1 = W1[(size_t)(c * 64 + k8 + jj * 2 + 1) * F + n];
            __nv_bfloat16 a0 = __float2bfloat16(w0), a1 = __float2bfloat16(w1);
            __nv_bfloat16 b0 = __float2bfloat16(w0 - __bfloat162float(a0));
            __nv_bfloat16 b1 = __float2bfloat16(w1 - __bfloat162float(a1));
            hi[jj] = pack_bf16x2(a0, a1);
            lo[jj] = pack_bf16x2(b0, b1);
        }
        uint32_t off = SMEM_SWIZZLE_128B((uint32_t)(n * 128 + k8 * 2)) >> 4;
        g_w1h_img[c * 512 + off] = make_uint4(hi[0], hi[1], hi[2], hi[3]);
        g_w1l_img[c * 512 + off] = make_uint4(lo[0], lo[1], lo[2], lo[3]);
    } else {                              // splitW2: 1024 granules
        int gid = (bx - 407) * 256 + tid;
        int n  = gid >> 3;
        int k8 = (gid & 7) * 8;
        const float* Wsrc = (n < 64) ? Wmu : Wvar;
        int nn = n & 63;
        uint32_t hi[4], lo[4];
#pragma unroll
        for (int jj = 0; jj < 4; jj++) {
            float w0 = Wsrc[(size_t)(k8 + jj * 2 + 0) * 64 + nn];
            float w1 = Wsrc[(size_t)(k8 + jj * 2 + 1) * 64 + nn];
            __nv_bfloat16 a0 = __float2bfloat16(w0), a1 = __float2bfloat16(w1);
            __nv_bfloat16 b0 = __float2bfloat16(w0 - __bfloat162float(a0));
            __nv_bfloat16 b1 = __float2bfloat16(w1 - __bfloat162float(a1));
            hi[jj] = pack_bf16x2(a0, a1);
            lo[jj] = pack_bf16x2(b0, b1);
        }
        uint32_t off = SMEM_SWIZZLE_128B((uint32_t)(n * 128 + k8 * 2)) >> 4;
        g_w2h_img[off] = make_uint4(hi[0], hi[1], hi[2], hi[3]);
        g_w2l_img[off] = make_uint4(lo[0], lo[1], lo[2], lo[3]);
    }
}

// ---------------- CSR build ------------------------------------------------
__global__ void k_hist(const int* __restrict__ ei) {
    int e = blockIdx.x * blockDim.x + threadIdx.x;
    if (e < NE) atomicAdd(&g_deg[ei[NE + e]], 1);
}
__global__ void k_scan_local() {
    __shared__ int s[1024];
    int t = threadIdx.x;
    int i = blockIdx.x * 1024 + t;
    int v = (i < NN) ? g_deg[i] : 0;
    if (i < NN) g_dinv[i] = rsqrtf((float)v + 1.0f);
    s[t] = v; __syncthreads();
    for (int off = 1; off < 1024; off <<= 1) {
        int x = (t >= off) ? s[t - off] : 0;
        __syncthreads();
        s[t] += x;
        __syncthreads();
    }
    if (i < NN) g_rowptr[i] = s[t] - v;
    if (t == 1023) g_blocksums[blockIdx.x] = s[1023];
}
__global__ void k_scan_finish() {
    __shared__ int s[128];
    __shared__ int s_off;
    int t  = threadIdx.x;
    int bx = blockIdx.x;
    if (t < NB) s[t] = g_blocksums[t];
    __syncthreads();
    if (t == 0) {
        int acc = 0;
        for (int k = 0; k < bx; k++) acc += s[k];
        s_off = acc;
    }
    __syncthreads();
    int i = bx * 1024 + t;
    if (i < NN) g_rowptr[i] += s_off;
}
__global__ void k_scatter(const int* __restrict__ ei) {
    int e = blockIdx.x * blockDim.x + threadIdx.x;
    if (e >= NE) return;
    int src = ei[e];
    int dst = ei[NE + e];
    int pos = g_rowptr[dst] + atomicAdd(&g_cursor[dst], 1);
    g_edge[pos] = make_int2(src, __float_as_int(g_dinv[src] * g_dinv[dst]));
}

// ---------------- GEMM1: pipelined mma.sync bf16, 3-pass split -------------
// 256 threads, M-tile 128 (8 warps x 16 rows), K chunks of 64, double-buffered.
// smem (96KB): [0,32K) xh x2 | [32K,64K) xl x2 | [64K,80K) wh x2 | [80K,96K) wl x2
__global__ void __launch_bounds__(256, 2) k_gemm1_mma(const float* __restrict__ x) {
    extern __shared__ char smem[];
    const uint32_t sb = smem_to_u32(smem);

    const int tid  = threadIdx.x;
    const int warp = tid >> 5;
    const int lane = tid & 31;
    const int row0 = blockIdx.x * 128;

    float acc[8][4];
#pragma unroll
    for (int nt = 0; nt < 8; nt++)
#pragma unroll
        for (int q = 0; q < 4; q++) acc[nt][q] = 0.f;

    const int lrow = lane & 7;
    const int sub  = lane >> 3;
    const int aRowOff = lrow + (sub & 1) * 8;
    const int aColOff = (sub >> 1) * 16;
    const int bRowOff = lrow + (sub >> 1) * 8;
    const int bColOff = (sub & 1) * 16;

    const int r_ = tid >> 4;
    const int g_ = tid & 15;
    float4 xr[8];

    // prologue
    {
        uint32_t whd = sb + 65536;
        uint32_t wld = sb + 81920;
#pragma unroll
        for (int l = 0; l < 2; l++) {
            int i = tid + l * 256;
            CP_ASYNC16(whd + i * 16, g_w1h_img + i);
            CP_ASYNC16(wld + i * 16, g_w1l_img + i);
        }
        CP_COMMIT();
#pragma unroll
        for (int l = 0; l < 8; l++) {
            int r = r_ + l * 16;
            int gr = row0 + r; if (gr > NN - 1) gr = NN - 1;
            xr[l] = *(const float4*)(x + (size_t)gr * KDIM + g_ * 4);
        }
        CP_WAIT0();
    }

    for (int c = 0; c < 8; c++) {
        const int b = c & 1;
        const uint32_t bXH = sb + b * 16384;
        const uint32_t bXL = sb + 32768 + b * 16384;
        const uint32_t bWH = sb + 65536 + b * 8192;
        const uint32_t bWL = sb + 81920 + b * 8192;

#pragma unroll
        for (int l = 0; l < 8; l++) {
            int r = r_ + l * 16;
            uint2 hi, lo;
            split4(xr[l], hi, lo);
            uint32_t off = SMEM_SWIZZLE_128B((uint32_t)(r * 128 + g_ * 8));
            *(uint2*)(smem + (bXH - sb) + off) = hi;
            *(uint2*)(smem + (bXL - sb) + off) = lo;
        }
        __syncthreads();

        if (c < 7) {
            const int b2 = (c + 1) & 1;
            uint32_t whd = sb + 65536 + b2 * 8192;
            uint32_t wld = sb + 81920 + b2 * 8192;
#pragma unroll
            for (int l = 0; l < 2; l++) {
                int i = tid + l * 256;
                CP_ASYNC16(whd + i * 16, g_w1h_img + (c + 1) * 512 + i);
                CP_ASYNC16(wld + i * 16, g_w1l_img + (c + 1) * 512 + i);
            }
            CP_COMMIT();
#pragma unroll
            for (int l = 0; l < 8; l++) {
                int r = r_ + l * 16;
                int gr = row0 + r; if (gr > NN - 1) gr = NN - 1;
                xr[l] = *(const float4*)(x + (size_t)gr * KDIM + (c + 1) * 64 + g_ * 4);
            }
        }

#pragma unroll
        for (int ks = 0; ks < 4; ks++) {
            const int kb = ks * 32;
            uint32_t ah[4], al[4];
            {
                uint32_t off = SMEM_SWIZZLE_128B(
                    (uint32_t)((warp * 16 + aRowOff) * 128 + kb + aColOff));
                ldsm_x4(ah[0], ah[1], ah[2], ah[3], bXH + off);
                ldsm_x4(al[0], al[1], al[2], al[3], bXL + off);
            }
            uint32_t bh[8][2], bl[8][2];
#pragma unroll
            for (int nb = 0; nb < 4; nb++) {
                uint32_t off = SMEM_SWIZZLE_128B(
                    (uint32_t)((nb * 16 + bRowOff) * 128 + kb + bColOff));
                ldsm_x4(bh[nb * 2][0], bh[nb * 2][1], bh[nb * 2 + 1][0],
                        bh[nb * 2 + 1][1], bWH + off);
                ldsm_x4(bl[nb * 2][0], bl[nb * 2][1], bl[nb * 2 + 1][0],
                        bl[nb * 2 + 1][1], bWL + off);
            }
#pragma unroll
            for (int nt = 0; nt < 8; nt++) {
                mma_bf16(acc[nt], ah, bh[nt]);
                mma_bf16(acc[nt], al, bh[nt]);
                mma_bf16(acc[nt], ah, bl[nt]);
            }
        }
        CP_WAIT0();
    }

    const int crow = lane >> 2;
    const int ccol = (lane & 3) * 2;
    int r = row0 + warp * 16 + crow;
#pragma unroll
    for (int nt = 0; nt < 8; nt++) {
        if (r < NN)
            *(float2*)(g_xw + (size_t)r * F + nt * 8 + ccol) =
                make_float2(acc[nt][0], acc[nt][1]);
        if (r + 8 < NN)
            *(float2*)(g_xw + (size_t)(r + 8) * F + nt * 8 + ccol) =
                make_float2(acc[nt][2], acc[nt][3]);
    }
}

// ---------------- aggregation: warp per node, 4-way unrolled gathers -------
__global__ void k_agg(const float* __restrict__ bias, int layer) {
    int node = (blockIdx.x * blockDim.x + threadIdx.x) >> 5;
    int lane = threadIdx.x & 31;
    if (node >= NN) return;
    const float* fin = (layer == 1) ? g_xw : g_h;
    float*       fout = (layer == 1) ? g_h : g_g;

    int start = g_rowptr[node];
    int end   = start + g_deg[node];
    float a0 = 0.f, a1 = 0.f, b0 = 0.f, b1 = 0.f;
    float c0 = 0.f, c1 = 0.f, d0 = 0.f, d1 = 0.f;
    int j = start;
    for (; j + 3 < end; j += 4) {
        int2 e0 = __ldg(&g_edge[j]);
        int2 e1 = __ldg(&g_edge[j + 1]);
        int2 e2 = __ldg(&g_edge[j + 2]);
        int2 e3 = __ldg(&g_edge[j + 3]);
        float2 v0 = __ldg((const float2*)(fin + (size_t)e0.x * F) + lane);
        float2 v1 = __ldg((const float2*)(fin + (size_t)e1.x * F) + lane);
        float2 v2 = __ldg((const float2*)(fin + (size_t)e2.x * F) + lane);
        float2 v3 = __ldg((const float2*)(fin + (size_t)e3.x * F) + lane);
        float w0 = __int_as_float(e0.y), w1 = __int_as_float(e1.y);
        float w2 = __int_as_float(e2.y), w3 = __int_as_float(e3.y);
        a0 += w0 * v0.x; a1 += w0 * v0.y;
        b0 += w1 * v1.x; b1 += w1 * v1.y;
        c0 += w2 * v2.x; c1 += w2 * v2.y;
        d0 += w3 * v3.x; d1 += w3 * v3.y;
    }
    for (; j < end; j++) {
        int2 e0 = __ldg(&g_edge[j]);
        float2 v0 = __ldg((const float2*)(fin + (size_t)e0.x * F) + lane);
        float w0 = __int_as_float(e0.y);
        a0 += w0 * v0.x; a1 += w0 * v0.y;
    }
    a0 = (a0 + b0) + (c0 + d0);
    a1 = (a1 + b1) + (c1 + d1);

    float di = g_dinv[node];
    float sw = di * di;
    float2 vs = ((const float2*)(fin + (size_t)node * F))[lane];
    a0 += sw * vs.x;
    a1 += sw * vs.y;
    if (layer == 1) {
        float2 bb = ((const float2*)bias)[lane];
        a0 = fmaxf(a0 + bb.x, 0.f);
        a1 = fmaxf(a1 + bb.y, 0.f);
    }
    ((float2*)(fout + (size_t)node * F))[lane] = make_float2(a0, a1);
}

// ---------------- GEMM2 via mma.sync bf16, 3-pass split + epilogue ---------
__global__ void __launch_bounds__(128) k_gemm2_mma(
    const float* __restrict__ bmu, const float* __restrict__ bvar,
    const float* __restrict__ eps, float* __restrict__ out) {
    __shared__ __align__(16) char s_gh[64 * 128];
    __shared__ __align__(16) char s_gl[64 * 128];
    __shared__ __align__(16) char s_wh[128 * 128];
    __shared__ __align__(16) char s_wl[128 * 128];

    const int tid  = threadIdx.x;
    const int warp = tid >> 5;
    const int lane = tid & 31;
    const int row0 = blockIdx.x * 64;

    const uint32_t bGH = smem_to_u32(s_gh);
    const uint32_t bGL = smem_to_u32(s_gl);
    const uint32_t bWH = smem_to_u32(s_wh);
    const uint32_t bWL = smem_to_u32(s_wl);

#pragma unroll
    for (int l = 0; l < 8; l++) {
        int idx = tid + l * 128;
        int g   = idx & 15;
        int r   = idx >> 4;
        int gr  = row0 + r; if (gr > NN - 1) gr = NN - 1;
        float4 v = *(const float4*)(g_g + (size_t)gr * F + g * 4);
        uint2 hi, lo;
        split4(v, hi, lo);
        uint32_t off = SMEM_SWIZZLE_128B((uint32_t)(r * 128 + g * 8));
        *(uint2*)(s_gh + off) = hi;
        *(uint2*)(s_gl + off) = lo;
    }
    {
        uint4* dH = (uint4*)s_wh;
        uint4* dL = (uint4*)s_wl;
#pragma unroll
        for (int l = 0; l < 8; l++) {
            int i = tid + l * 128;
            dH[i] = g_w2h_img[i];
            dL[i] = g_w2l_img[i];
        }
    }
    __syncthreads();

    float acc[16][4];
#pragma unroll
    for (int nt = 0; nt < 16; nt++)
#pragma unroll
        for (int q = 0; q < 4; q++) acc[nt][q] = 0.f;

    const int lrow = lane & 7;
    const int sub  = lane >> 3;
    const int aRowOff = lrow + (sub & 1) * 8;
    const int aColOff = (sub >> 1) * 16;
    const int bRowOff = lrow + (sub >> 1) * 8;
    const int bColOff = (sub & 1) * 16;

#pragma unroll
    for (int ks = 0; ks < 4; ks++) {
        const int kb = ks * 32;
        uint32_t ah[4], al[4];
        {
            uint32_t off = SMEM_SWIZZLE_128B(
                (uint32_t)((warp * 16 + aRowOff) * 128 + kb + aColOff));
            ldsm_x4(ah[0], ah[1], ah[2], ah[3], bGH + off);
            ldsm_x4(al[0], al[1], al[2], al[3], bGL + off);
        }
#pragma unroll
        for (int nb = 0; nb < 8; nb++) {
            uint32_t off = SMEM_SWIZZLE_128B(
                (uint32_t)((nb * 16 + bRowOff) * 128 + kb + bColOff));
            uint32_t h0, h1, h2, h3, l0, l1, l2, l3;
            ldsm_x4(h0, h1, h2, h3, bWH + off);
            ldsm_x4(l0, l1, l2, l3, bWL + off);
            uint32_t bhA[2] = {h0, h1}, bhB[2] = {h2, h3};
            uint32_t blA[2] = {l0, l1}, blB[2] = {l2, l3};
            mma_bf16(acc[nb * 2],     ah, bhA);
            mma_bf16(acc[nb * 2],     al, bhA);
            mma_bf16(acc[nb * 2],     ah, blA);
            mma_bf16(acc[nb * 2 + 1], ah, bhB);
            mma_bf16(acc[nb * 2 + 1], al, bhB);
            mma_bf16(acc[nb * 2 + 1], ah, blB);
        }
    }

    const int crow  = lane >> 2;
    const int ccol  = (lane & 3) * 2;
    const size_t secz = (size_t)NN * F;
#pragma unroll
    for (int half = 0; half < 2; half++) {
        int r = row0 + warp * 16 + crow + half * 8;
        if (r >= NN) continue;
#pragma unroll
        for (int nt = 0; nt < 8; nt++) {
            int col = nt * 8 + ccol;
            float mu0 = acc[nt][half * 2 + 0]     + bmu[col];
            float mu1 = acc[nt][half * 2 + 1]     + bmu[col + 1];
            float vl0 = acc[nt + 8][half * 2 + 0] + bvar[col];
            float vl1 = acc[nt + 8][half * 2 + 1] + bvar[col + 1];
            float sp0 = fmaxf(vl0, 0.f) + log1pf(expf(-fabsf(vl0)));
            float sp1 = fmaxf(vl1, 0.f) + log1pf(expf(-fabsf(vl1)));
            float2 e  = *(const float2*)(eps + (size_t)r * F + col);
            size_t off = (size_t)r * F + col;
            *(float2*)(out + off)            = make_float2(mu0, mu1);
            *(float2*)(out + secz + off)     = make_float2(sp0, sp1);
            *(float2*)(out + 2 * secz + off) = make_float2(mu0 + sp0 * e.x,
                                                           mu1 + sp1 * e.y);
        }
    }
}

// ---------------- launch ---------------------------------------------------
extern "C" void kernel_launch(void* const* d_in, const int* in_sizes, int n_in,
                              void* d_out, int out_size) {
    const float* x    = (const float*)d_in[0];
    const int*   ei   = (const int*)d_in[1];    // edge_index is int32
    const float* W1   = (const float*)d_in[2];
    const float* b1   = (const float*)d_in[3];
    const float* Wmu  = (const float*)d_in[4];
    const float* bmu  = (const float*)d_in[5];
    const float* Wvar = (const float*)d_in[6];
    const float* bvar = (const float*)d_in[7];
    const float* eps  = (const float*)d_in[8];
    float*       out  = (float*)d_out;

    // one-time host objects (identical GPU work every call; no device memory)
    static cudaStream_t s2 = nullptr;
    static cudaEvent_t evFork = nullptr, evJoin = nullptr;
    if (s2 == nullptr) {
        cudaStreamCreateWithFlags(&s2, cudaStreamNonBlocking);
        cudaEventCreateWithFlags(&evFork, cudaEventDisableTiming);
        cudaEventCreateWithFlags(&evJoin, cudaEventDisableTiming);
        cudaFuncSetAttribute(k_gemm1_mma,
                             cudaFuncAttributeMaxDynamicSharedMemorySize, 98304);
    }

    // prep: zero deg/cursor + pre-split both weight sets (one launch)
    k_prep<<<411, 256>>>(W1, Wmu, Wvar);

    // fork: GEMM1 (branch s2) runs concurrently with the CSR chain (main)
    cudaEventRecord(evFork, 0);
    cudaStreamWaitEvent(s2, evFork, 0);
    k_gemm1_mma<<<(NN + 127) / 128, 256, 98304, s2>>>(x);
    cudaEventRecord(evJoin, s2);

    // main branch: CSR build
    k_hist       <<<(NE + 255) / 256, 256>>>(ei);
    k_scan_local <<<NB, 1024>>>();
    k_scan_finish<<<NB, 1024>>>();
    k_scatter    <<<(NE + 255) / 256, 256>>>(ei);

    // join: agg1 needs both g_xw (s2) and g_edge (main)
    cudaStreamWaitEvent(0, evJoin, 0);

    k_agg      <<<(NN + 7) / 8, 256>>>(b1, 1);
    k_agg      <<<(NN + 7) / 8, 256>>>(nullptr, 2);
    k_gemm2_mma<<<(NN + 63) / 64, 128>>>(bmu, bvar, eps, out);
}